// round 2
// baseline (speedup 1.0000x reference)
#include <cuda_runtime.h>
#include <math.h>

// Problem constants (fixed by the dataset)
#define Bb   4
#define Ss   2048
#define Dd   512
#define Hh   8
#define DK   64
#define Rr   8
#define TR   16                     // 2R
#define NBH  (Bb*Hh)                // 32
#define NNODES (NBH*Ss)             // 65536
#define NEDGE  (NBH*TR*Ss)          // 1048576

// ---------------- scratch (device globals; no allocation allowed) -------------
__device__ float g_q[NBH*Ss*DK];
__device__ float g_k[NBH*Ss*DK];
__device__ float g_v[NBH*Ss*DK];
__device__ float g_e[NEDGE];
__device__ int   g_cnt[NNODES];
__device__ int   g_off[NBH*(Ss+1)];
__device__ int   g_info[NEDGE];
__device__ float g_val[NEDGE];
__device__ float g_attn[Bb*Ss*Dd];   // [B,S,H,dk]

// ---------------- GEMM: C[m,n] = sum_k A[m,k]*W[n,k] + bias[n] ----------------
// M = 8192, N = 512, K = 512.  BM=128, BN=64, BK=16, 256 threads, 8x4/thread.
#define BM 128
#define BN 64
#define BKK 16

// mode: 0->write g_q (qkv layout), 1->g_k, 2->g_v, 3->A=g_attn, write C_ext flat
__global__ __launch_bounds__(256) void gemm_nt(
    const float* __restrict__ A_ext, const float* __restrict__ W,
    const float* __restrict__ bias, float* __restrict__ C_ext, int mode)
{
    __shared__ float As[BKK][BM+4];
    __shared__ float Bs[BKK][BN+4];

    const float* A = (mode == 3) ? (const float*)g_attn : A_ext;
    float* dst = (mode == 0) ? g_q : (mode == 1) ? g_k : (mode == 2) ? g_v : C_ext;

    const int tid = threadIdx.x;
    const int m0 = blockIdx.y * BM;
    const int n0 = blockIdx.x * BN;

    const int arow = tid >> 1;          // 0..127
    const int acol = (tid & 1) * 8;     // 0 or 8
    const int brow = tid >> 2;          // 0..63
    const int bcol = (tid & 3) * 4;     // 0,4,8,12

    const float* Aptr = A + (size_t)(m0 + arow) * Dd + acol;
    const float* Wptr = W + (size_t)(n0 + brow) * Dd + bcol;

    float acc[8][4];
#pragma unroll
    for (int i = 0; i < 8; i++)
#pragma unroll
        for (int j = 0; j < 4; j++) acc[i][j] = 0.f;

    const int ty = tid >> 4;   // 0..15
    const int tx = tid & 15;   // 0..15

    for (int k0 = 0; k0 < Dd; k0 += BKK) {
        float4 a0 = *(const float4*)(Aptr + k0);
        float4 a1 = *(const float4*)(Aptr + k0 + 4);
        float4 bb = *(const float4*)(Wptr + k0);
        As[acol + 0][arow] = a0.x; As[acol + 1][arow] = a0.y;
        As[acol + 2][arow] = a0.z; As[acol + 3][arow] = a0.w;
        As[acol + 4][arow] = a1.x; As[acol + 5][arow] = a1.y;
        As[acol + 6][arow] = a1.z; As[acol + 7][arow] = a1.w;
        Bs[bcol + 0][brow] = bb.x; Bs[bcol + 1][brow] = bb.y;
        Bs[bcol + 2][brow] = bb.z; Bs[bcol + 3][brow] = bb.w;
        __syncthreads();
#pragma unroll
        for (int kk = 0; kk < BKK; kk++) {
            float4 af0 = *(const float4*)&As[kk][ty * 8];
            float4 af1 = *(const float4*)&As[kk][ty * 8 + 4];
            float4 bf  = *(const float4*)&Bs[kk][tx * 4];
            float a[8] = {af0.x, af0.y, af0.z, af0.w, af1.x, af1.y, af1.z, af1.w};
            float b[4] = {bf.x, bf.y, bf.z, bf.w};
#pragma unroll
            for (int i = 0; i < 8; i++)
#pragma unroll
                for (int j = 0; j < 4; j++) acc[i][j] += a[i] * b[j];
        }
        __syncthreads();
    }

    const int nb = n0 + tx * 4;
    float4 bias4;
    bias4.x = bias[nb + 0]; bias4.y = bias[nb + 1];
    bias4.z = bias[nb + 2]; bias4.w = bias[nb + 3];

#pragma unroll
    for (int i = 0; i < 8; i++) {
        int m = m0 + ty * 8 + i;
        float4 o;
        o.x = acc[i][0] + bias4.x; o.y = acc[i][1] + bias4.y;
        o.z = acc[i][2] + bias4.z; o.w = acc[i][3] + bias4.w;
        if (mode == 3) {
            *(float4*)&dst[(size_t)m * Dd + nb] = o;
        } else {
            int b = m >> 11, s = m & (Ss - 1);
            int h = nb >> 6, d = nb & 63;
            *(float4*)&dst[(size_t)(((b * Hh + h) * Ss + s)) * DK + d] = o;
        }
    }
}

// ---------------- zero counters -------------------------------------------
__global__ void k_zero()
{
    int i = blockIdx.x * 256 + threadIdx.x;
    if (i < NNODES) g_cnt[i] = 0;
}

// ---------------- per-edge score + exp + count -----------------------------
// 16 lanes per edge; edge e = ((b*H+h)*16 + j)*S + s
__global__ __launch_bounds__(256) void k_edges(
    const int* __restrict__ snod, const int* __restrict__ enod,
    const float* __restrict__ rq, const float* __restrict__ rk)
{
    int gt = blockIdx.x * 256 + threadIdx.x;
    int e = gt >> 4;
    int sub = gt & 15;
    int s = e & (Ss - 1);
    int j = (e >> 11) & 15;
    int bh = e >> 15;
    int h = bh & (Hh - 1);
    int jm = j & (Rr - 1);
    int nidx = (bh * Rr + jm) * Ss + s;
    int sv = snod[nidx];
    int ev = enod[nidx];
    bool masked = (j == 0) || (sv < 0);
    int s0 = sv < 0 ? 0 : sv;
    int qn = (j < Rr) ? ev : s0;
    int kn = (j < Rr) ? s0 : ev;
    qn &= (Ss - 1); kn &= (Ss - 1);   // memory safety

    const float4 qv  = *(const float4*)&g_q[(size_t)(bh * Ss + qn) * DK + sub * 4];
    const float4 kv  = *(const float4*)&g_k[(size_t)(bh * Ss + kn) * DK + sub * 4];
    const float4 rqv = *(const float4*)&rq[(h * TR + j) * DK + sub * 4];
    const float4 rkv = *(const float4*)&rk[(h * TR + j) * DK + sub * 4];

    // score = q.(k+rk) + rq.k
    float p = qv.x * (kv.x + rkv.x) + rqv.x * kv.x
            + qv.y * (kv.y + rkv.y) + rqv.y * kv.y
            + qv.z * (kv.z + rkv.z) + rqv.z * kv.z
            + qv.w * (kv.w + rkv.w) + rqv.w * kv.w;
#pragma unroll
    for (int off = 8; off; off >>= 1)
        p += __shfl_xor_sync(0xffffffffu, p, off);

    if (sub == 0 && !masked) {
        float exv = __expf(p * (1.0f / 24.0f));   // /(3*sqrt(64))
        g_e[e] = exv;
        atomicAdd(&g_cnt[bh * Ss + qn], 1);
    }
}

// ---------------- exclusive scan of per-node counts per (b,h) --------------
__global__ __launch_bounds__(256) void k_scan()
{
    __shared__ int partial[256];
    int bh = blockIdx.x;
    int t = threadIdx.x;
    int base = bh * Ss + t * 8;
    int c[8]; int sum = 0;
#pragma unroll
    for (int i = 0; i < 8; i++) { c[i] = g_cnt[base + i]; sum += c[i]; }
    partial[t] = sum;
    __syncthreads();
    for (int off = 1; off < 256; off <<= 1) {
        int v = (t >= off) ? partial[t - off] : 0;
        __syncthreads();
        partial[t] += v;
        __syncthreads();
    }
    int run = partial[t] - sum;     // exclusive prefix of this chunk
    int obase = bh * (Ss + 1) + t * 8;
#pragma unroll
    for (int i = 0; i < 8; i++) { g_off[obase + i] = run; run += c[i]; }
    if (t == 255) g_off[bh * (Ss + 1) + Ss] = run;
    // reset counters: reused as insertion cursors in k_fill
#pragma unroll
    for (int i = 0; i < 8; i++) g_cnt[base + i] = 0;
}

// ---------------- CSR fill ---------------------------------------------------
__global__ __launch_bounds__(256) void k_fill(
    const int* __restrict__ snod, const int* __restrict__ enod)
{
    int e = blockIdx.x * 256 + threadIdx.x;
    int s = e & (Ss - 1);
    int j = (e >> 11) & 15;
    int bh = e >> 15;
    int jm = j & (Rr - 1);
    int nidx = (bh * Rr + jm) * Ss + s;
    int sv = snod[nidx];
    if (j == 0 || sv < 0) return;
    int ev = enod[nidx];
    int qn = (j < Rr) ? ev : sv;
    int kn = (j < Rr) ? sv : ev;
    qn &= (Ss - 1); kn &= (Ss - 1);
    int pos = g_off[bh * (Ss + 1) + qn] + atomicAdd(&g_cnt[bh * Ss + qn], 1);
    int idx = bh * (TR * Ss) + pos;
    g_info[idx] = kn | (j << 12);
    g_val[idx] = g_e[e];
}

// ---------------- per-node gather + softmax + weighted sum -------------------
// one warp per node; lane d and d+32 over dk=64
__global__ __launch_bounds__(256) void k_aggr(const float* __restrict__ rv)
{
    int w = (blockIdx.x * 256 + threadIdx.x) >> 5;
    int lane = threadIdx.x & 31;
    int bh = w >> 11;
    int n = w & (Ss - 1);
    int h = bh & (Hh - 1), b = bh >> 3;
    int obase = bh * (Ss + 1) + n;
    int beg = g_off[obase], end = g_off[obase + 1];
    float acc0 = 0.f, acc1 = 0.f, ds = 0.f;
    int cbase = bh * (TR * Ss);
    for (int i = beg; i < end; i++) {
        int info = g_info[cbase + i];
        float evv = g_val[cbase + i];
        int kn = info & 0xFFF;
        int j = info >> 12;
        size_t vb = (size_t)(bh * Ss + kn) * DK;
        int rb = (h * TR + j) * DK;
        acc0 += evv * (g_v[vb + lane] + rv[rb + lane]);
        acc1 += evv * (g_v[vb + 32 + lane] + rv[rb + 32 + lane]);
        ds += evv;
    }
    float inv = ds > 0.f ? 1.f / ds : 0.f;
    size_t ob = (size_t)((b * Ss + n) * Hh + h) * DK;   // [B,S,H,dk]
    g_attn[ob + lane] = acc0 * inv;
    g_attn[ob + 32 + lane] = acc1 * inv;
}

// ---------------- launch --------------------------------------------------
extern "C" void kernel_launch(void* const* d_in, const int* in_sizes, int n_in,
                              void* d_out, int out_size)
{
    const float* query = (const float*)d_in[0];
    const float* key   = (const float*)d_in[1];
    const float* value = (const float*)d_in[2];
    const int*   snod  = (const int*)d_in[3];
    const int*   enod  = (const int*)d_in[4];
    const float* rel_q = (const float*)d_in[5];
    const float* rel_k = (const float*)d_in[6];
    const float* rel_v = (const float*)d_in[7];
    const float* Wq = (const float*)d_in[8];
    const float* bq = (const float*)d_in[9];
    const float* Wk = (const float*)d_in[10];
    const float* bk = (const float*)d_in[11];
    const float* Wv = (const float*)d_in[12];
    const float* bv = (const float*)d_in[13];
    const float* Wo = (const float*)d_in[14];
    const float* bo = (const float*)d_in[15];
    float* out = (float*)d_out;

    dim3 gg(Dd / BN, (Bb * Ss) / BM);   // (8, 64)

    k_zero<<<NNODES / 256, 256>>>();
    gemm_nt<<<gg, 256>>>(query, Wq, bq, nullptr, 0);
    gemm_nt<<<gg, 256>>>(key,   Wk, bk, nullptr, 1);
    gemm_nt<<<gg, 256>>>(value, Wv, bv, nullptr, 2);
    k_edges<<<(size_t)NEDGE * 16 / 256, 256>>>(snod, enod, rel_q, rel_k);
    k_scan<<<NBH, 256>>>();
    k_fill<<<NEDGE / 256, 256>>>(snod, enod);
    k_aggr<<<NNODES * 32 / 256, 256>>>(rel_v);
    gemm_nt<<<gg, 256>>>(nullptr, Wo, bo, out, 3);
}

// round 4
// speedup vs baseline: 1.7392x; 1.7392x over previous
#include <cuda_runtime.h>
#include <cuda_bf16.h>
#include <math.h>

// Problem constants (fixed by the dataset)
#define Bb   4
#define Ss   2048
#define Dd   512
#define Hh   8
#define DK   64
#define Rr   8
#define TR   16
#define NBH  (Bb*Hh)                // 32
#define NNODES (NBH*Ss)             // 65536
#define NEDGE  (NBH*TR*Ss)          // 1048576

// ---------------- scratch (device globals; no allocation allowed) -------------
__device__ float g_q[NBH*Ss*DK];
__device__ float g_k[NBH*Ss*DK];
__device__ float g_v[NBH*Ss*DK];
__device__ float g_e[NEDGE];
__device__ int   g_cnt[NNODES];
__device__ int   g_off[NBH*(Ss+1)];
__device__ int   g_info[NEDGE];
__device__ float g_val[NEDGE];
__device__ float g_attn[Bb*Ss*Dd];   // row m=b*S+s, col h*64+d

// ======================= small helpers =======================================
__device__ __forceinline__ unsigned su32(const void* p){
    unsigned a;
    asm("{ .reg .u64 t; cvta.to.shared.u64 t, %1; cvt.u32.u64 %0, t; }"
        : "=r"(a) : "l"(p));
    return a;
}
__device__ __forceinline__ unsigned packbf2(float x, float y){
    __nv_bfloat162 t = __floats2bfloat162_rn(x, y);
    return *(unsigned*)&t;
}
__device__ __forceinline__ void sts128(unsigned a, unsigned x, unsigned y,
                                       unsigned z, unsigned w){
    asm volatile("st.shared.v4.b32 [%0], {%1,%2,%3,%4};"
                 :: "r"(a), "r"(x), "r"(y), "r"(z), "r"(w) : "memory");
}
__device__ __forceinline__ void ldmx4(unsigned* r, unsigned addr){
    asm volatile("ldmatrix.sync.aligned.m8n8.x4.shared.b16 {%0,%1,%2,%3}, [%4];"
                 : "=r"(r[0]), "=r"(r[1]), "=r"(r[2]), "=r"(r[3]) : "r"(addr));
}
__device__ __forceinline__ void mma_bf16(float* d, const unsigned* a, const unsigned* b){
    asm volatile(
        "mma.sync.aligned.m16n8k16.row.col.f32.bf16.bf16.f32 "
        "{%0,%1,%2,%3}, {%4,%5,%6,%7}, {%8,%9}, {%0,%1,%2,%3};"
        : "+f"(d[0]), "+f"(d[1]), "+f"(d[2]), "+f"(d[3])
        : "r"(a[0]), "r"(a[1]), "r"(a[2]), "r"(a[3]), "r"(b[0]), "r"(b[1]));
}
// 64-byte rows, 16B-granule XOR swizzle: conflict-free ldmatrix
__device__ __forceinline__ unsigned swz(unsigned row, unsigned kb){
    return row * 64u + ((((kb >> 4) ^ ((row >> 1) & 3u)) << 4) | (kb & 15u));
}

// ================= tensor-core GEMM: C[m,n]=sum_k A[m,k]*W[n,k]+bias[n] =======
// M=8192, N=512, K=512. BM=128, BN=128, BK=32, 256 thr, 8 warps (4M x 2N).
// 3-term bf16 split: hi*hi + hi*lo + lo*hi (fp32-grade accuracy).
// mode: 0->g_q (qkv layout), 1->g_k, 2->g_v, 3->A=g_attn, C=C_ext flat
#define STG_A_H 0
#define STG_A_L 8192
#define STG_B_H 16384
#define STG_B_L 24576
#define STG_SZ  32768

__global__ __launch_bounds__(256) void gemm_tc(
    const float* __restrict__ A_ext, const float* __restrict__ W,
    const float* __restrict__ bias, float* __restrict__ C_ext, int mode)
{
    extern __shared__ char dsm[];
    const unsigned sbase = su32(dsm);

    const float* A = (mode == 3) ? (const float*)g_attn : A_ext;
    float* dst = (mode == 0) ? g_q : (mode == 1) ? g_k : (mode == 2) ? g_v : C_ext;

    const int tid = threadIdx.x;
    const int wid = tid >> 5, lane = tid & 31;
    const int wm = wid & 3, wn = wid >> 2;
    const int m0 = blockIdx.y * 128, n0 = blockIdx.x * 128;

    // global-load mapping: row = tid>>1 (0..127), half h = tid&1 (k 16-float chunk)
    const int grow = tid >> 1, gh = tid & 1;
    const float* Aptr = A + (size_t)(m0 + grow) * Dd + gh * 16;
    const float* Wptr = W + (size_t)(n0 + grow) * Dd + gh * 16;

    float acc[2][8][4];
#pragma unroll
    for (int mt = 0; mt < 2; mt++)
#pragma unroll
        for (int nt = 0; nt < 8; nt++)
#pragma unroll
            for (int i = 0; i < 4; i++) acc[mt][nt][i] = 0.f;

    float4 pa[4], pb[4];
    // prologue: chunk 0 gmem -> regs
#pragma unroll
    for (int i = 0; i < 4; i++) {
        pa[i] = *(const float4*)(Aptr + i * 4);
        pb[i] = *(const float4*)(Wptr + i * 4);
    }
    // regs -> smem stage 0
    {
        unsigned hi[8], lo[8];
#pragma unroll
        for (int i = 0; i < 4; i++) {
            float hx = __bfloat162float(__float2bfloat16(pa[i].x));
            float hy = __bfloat162float(__float2bfloat16(pa[i].y));
            float hz = __bfloat162float(__float2bfloat16(pa[i].z));
            float hw = __bfloat162float(__float2bfloat16(pa[i].w));
            hi[2*i] = packbf2(hx, hy); hi[2*i+1] = packbf2(hz, hw);
            lo[2*i] = packbf2(pa[i].x - hx, pa[i].y - hy);
            lo[2*i+1] = packbf2(pa[i].z - hz, pa[i].w - hw);
        }
        unsigned s0 = sbase + STG_A_H + swz(grow, gh*32);
        unsigned s1 = sbase + STG_A_H + swz(grow, gh*32+16);
        sts128(s0, hi[0],hi[1],hi[2],hi[3]); sts128(s1, hi[4],hi[5],hi[6],hi[7]);
        s0 = sbase + STG_A_L + swz(grow, gh*32); s1 = sbase + STG_A_L + swz(grow, gh*32+16);
        sts128(s0, lo[0],lo[1],lo[2],lo[3]); sts128(s1, lo[4],lo[5],lo[6],lo[7]);
#pragma unroll
        for (int i = 0; i < 4; i++) {
            float hx = __bfloat162float(__float2bfloat16(pb[i].x));
            float hy = __bfloat162float(__float2bfloat16(pb[i].y));
            float hz = __bfloat162float(__float2bfloat16(pb[i].z));
            float hw = __bfloat162float(__float2bfloat16(pb[i].w));
            hi[2*i] = packbf2(hx, hy); hi[2*i+1] = packbf2(hz, hw);
            lo[2*i] = packbf2(pb[i].x - hx, pb[i].y - hy);
            lo[2*i+1] = packbf2(pb[i].z - hz, pb[i].w - hw);
        }
        s0 = sbase + STG_B_H + swz(grow, gh*32); s1 = sbase + STG_B_H + swz(grow, gh*32+16);
        sts128(s0, hi[0],hi[1],hi[2],hi[3]); sts128(s1, hi[4],hi[5],hi[6],hi[7]);
        s0 = sbase + STG_B_L + swz(grow, gh*32); s1 = sbase + STG_B_L + swz(grow, gh*32+16);
        sts128(s0, lo[0],lo[1],lo[2],lo[3]); sts128(s1, lo[4],lo[5],lo[6],lo[7]);
    }
    __syncthreads();

    for (int c = 0; c < 16; c++) {
        // issue next chunk's LDGs early (latency hidden by MMAs below)
        if (c + 1 < 16) {
#pragma unroll
            for (int i = 0; i < 4; i++) {
                pa[i] = *(const float4*)(Aptr + (c + 1) * 32 + i * 4);
                pb[i] = *(const float4*)(Wptr + (c + 1) * 32 + i * 4);
            }
        }
        // compute on stage c&1
        const unsigned stg = sbase + (c & 1) * STG_SZ;
#pragma unroll
        for (int ks = 0; ks < 2; ks++) {
            const unsigned kb = ks * 32;
            unsigned ah[2][4], al[2][4], bh[8][2], bl[8][2];
            // A fragments: rows wm*32 + mt*16 + (lane&15), col kb + (lane>>4)*16
#pragma unroll
            for (int mt = 0; mt < 2; mt++) {
                unsigned r = wm * 32 + mt * 16 + (lane & 15);
                unsigned kbyte = kb + (lane >> 4) * 16;
                ldmx4(ah[mt], stg + STG_A_H + swz(r, kbyte));
                ldmx4(al[mt], stg + STG_A_L + swz(r, kbyte));
            }
            // B fragments (pairs of n-tiles per x4)
#pragma unroll
            for (int p = 0; p < 4; p++) {
                unsigned r = wn * 64 + p * 16 + (lane & 7) + ((lane >> 4) << 3);
                unsigned kbyte = kb + ((lane >> 3) & 1) * 16;
                unsigned t[4];
                ldmx4(t, stg + STG_B_H + swz(r, kbyte));
                bh[2*p][0] = t[0]; bh[2*p][1] = t[1];
                bh[2*p+1][0] = t[2]; bh[2*p+1][1] = t[3];
                ldmx4(t, stg + STG_B_L + swz(r, kbyte));
                bl[2*p][0] = t[0]; bl[2*p][1] = t[1];
                bl[2*p+1][0] = t[2]; bl[2*p+1][1] = t[3];
            }
#pragma unroll
            for (int mt = 0; mt < 2; mt++)
#pragma unroll
                for (int nt = 0; nt < 8; nt++) {
                    mma_bf16(acc[mt][nt], ah[mt], bh[nt]);
                    mma_bf16(acc[mt][nt], ah[mt], bl[nt]);
                    mma_bf16(acc[mt][nt], al[mt], bh[nt]);
                }
        }
        // convert + store next chunk into the other stage
        if (c + 1 < 16) {
            const unsigned nstg = sbase + ((c + 1) & 1) * STG_SZ;
            unsigned hi[8], lo[8];
#pragma unroll
            for (int i = 0; i < 4; i++) {
                float hx = __bfloat162float(__float2bfloat16(pa[i].x));
                float hy = __bfloat162float(__float2bfloat16(pa[i].y));
                float hz = __bfloat162float(__float2bfloat16(pa[i].z));
                float hw = __bfloat162float(__float2bfloat16(pa[i].w));
                hi[2*i] = packbf2(hx, hy); hi[2*i+1] = packbf2(hz, hw);
                lo[2*i] = packbf2(pa[i].x - hx, pa[i].y - hy);
                lo[2*i+1] = packbf2(pa[i].z - hz, pa[i].w - hw);
            }
            unsigned s0 = nstg + STG_A_H + swz(grow, gh*32);
            unsigned s1 = nstg + STG_A_H + swz(grow, gh*32+16);
            sts128(s0, hi[0],hi[1],hi[2],hi[3]); sts128(s1, hi[4],hi[5],hi[6],hi[7]);
            s0 = nstg + STG_A_L + swz(grow, gh*32); s1 = nstg + STG_A_L + swz(grow, gh*32+16);
            sts128(s0, lo[0],lo[1],lo[2],lo[3]); sts128(s1, lo[4],lo[5],lo[6],lo[7]);
#pragma unroll
            for (int i = 0; i < 4; i++) {
                float hx = __bfloat162float(__float2bfloat16(pb[i].x));
                float hy = __bfloat162float(__float2bfloat16(pb[i].y));
                float hz = __bfloat162float(__float2bfloat16(pb[i].z));
                float hw = __bfloat162float(__float2bfloat16(pb[i].w));
                hi[2*i] = packbf2(hx, hy); hi[2*i+1] = packbf2(hz, hw);
                lo[2*i] = packbf2(pb[i].x - hx, pb[i].y - hy);
                lo[2*i+1] = packbf2(pb[i].z - hz, pb[i].w - hw);
            }
            s0 = nstg + STG_B_H + swz(grow, gh*32); s1 = nstg + STG_B_H + swz(grow, gh*32+16);
            sts128(s0, hi[0],hi[1],hi[2],hi[3]); sts128(s1, hi[4],hi[5],hi[6],hi[7]);
            s0 = nstg + STG_B_L + swz(grow, gh*32); s1 = nstg + STG_B_L + swz(grow, gh*32+16);
            sts128(s0, lo[0],lo[1],lo[2],lo[3]); sts128(s1, lo[4],lo[5],lo[6],lo[7]);
        }
        __syncthreads();
    }

    // -------- epilogue: fragments -> gmem with bias --------
#pragma unroll
    for (int nt = 0; nt < 8; nt++) {
        const int ncol = n0 + wn * 64 + nt * 8 + 2 * (lane & 3);
        const float b0 = bias[ncol], b1 = bias[ncol + 1];
#pragma unroll
        for (int mt = 0; mt < 2; mt++) {
            const int r0 = m0 + wm * 32 + mt * 16 + (lane >> 2);
            float2 v0 = make_float2(acc[mt][nt][0] + b0, acc[mt][nt][1] + b1);
            float2 v1 = make_float2(acc[mt][nt][2] + b0, acc[mt][nt][3] + b1);
            if (mode == 3) {
                *(float2*)(dst + (size_t)r0 * Dd + ncol) = v0;
                *(float2*)(dst + (size_t)(r0 + 8) * Dd + ncol) = v1;
            } else {
                const int h = ncol >> 6, d = ncol & 63;
                int b = r0 >> 11, s = r0 & (Ss - 1);
                *(float2*)(dst + (size_t)(((b * Hh + h) * Ss + s)) * DK + d) = v0;
                b = (r0 + 8) >> 11; s = (r0 + 8) & (Ss - 1);
                *(float2*)(dst + (size_t)(((b * Hh + h) * Ss + s)) * DK + d) = v1;
            }
        }
    }
}

// ---------------- zero counters -------------------------------------------
__global__ void k_zero()
{
    int i = blockIdx.x * 256 + threadIdx.x;
    if (i < NNODES) g_cnt[i] = 0;
}

// ---------------- per-edge score + exp + count -----------------------------
__global__ __launch_bounds__(256) void k_edges(
    const int* __restrict__ snod, const int* __restrict__ enod,
    const float* __restrict__ rq, const float* __restrict__ rk)
{
    int gt = blockIdx.x * 256 + threadIdx.x;
    int e = gt >> 4;
    int sub = gt & 15;
    int s = e & (Ss - 1);
    int j = (e >> 11) & 15;
    int bh = e >> 15;
    int h = bh & (Hh - 1);
    int jm = j & (Rr - 1);
    int nidx = (bh * Rr + jm) * Ss + s;
    int sv = snod[nidx];
    int ev = enod[nidx];
    bool masked = (j == 0) || (sv < 0);
    int s0 = sv < 0 ? 0 : sv;
    int qn = (j < Rr) ? ev : s0;
    int kn = (j < Rr) ? s0 : ev;
    qn &= (Ss - 1); kn &= (Ss - 1);

    const float4 qv  = *(const float4*)&g_q[(size_t)(bh * Ss + qn) * DK + sub * 4];
    const float4 kv  = *(const float4*)&g_k[(size_t)(bh * Ss + kn) * DK + sub * 4];
    const float4 rqv = *(const float4*)&rq[(h * TR + j) * DK + sub * 4];
    const float4 rkv = *(const float4*)&rk[(h * TR + j) * DK + sub * 4];

    float p = qv.x * (kv.x + rkv.x) + rqv.x * kv.x
            + qv.y * (kv.y + rkv.y) + rqv.y * kv.y
            + qv.z * (kv.z + rkv.z) + rqv.z * kv.z
            + qv.w * (kv.w + rkv.w) + rqv.w * kv.w;
#pragma unroll
    for (int off = 8; off; off >>= 1)
        p += __shfl_xor_sync(0xffffffffu, p, off);

    if (sub == 0 && !masked) {
        float exv = __expf(p * (1.0f / 24.0f));
        g_e[e] = exv;
        atomicAdd(&g_cnt[bh * Ss + qn], 1);
    }
}

// ---------------- exclusive scan of per-node counts per (b,h) --------------
__global__ __launch_bounds__(256) void k_scan()
{
    __shared__ int partial[256];
    int bh = blockIdx.x;
    int t = threadIdx.x;
    int base = bh * Ss + t * 8;
    int c[8]; int sum = 0;
#pragma unroll
    for (int i = 0; i < 8; i++) { c[i] = g_cnt[base + i]; sum += c[i]; }
    partial[t] = sum;
    __syncthreads();
    for (int off = 1; off < 256; off <<= 1) {
        int v = (t >= off) ? partial[t - off] : 0;
        __syncthreads();
        partial[t] += v;
        __syncthreads();
    }
    int run = partial[t] - sum;
    int obase = bh * (Ss + 1) + t * 8;
#pragma unroll
    for (int i = 0; i < 8; i++) { g_off[obase + i] = run; run += c[i]; }
    if (t == 255) g_off[bh * (Ss + 1) + Ss] = run;
#pragma unroll
    for (int i = 0; i < 8; i++) g_cnt[base + i] = 0;
}

// ---------------- CSR fill ---------------------------------------------------
__global__ __launch_bounds__(256) void k_fill(
    const int* __restrict__ snod, const int* __restrict__ enod)
{
    int e = blockIdx.x * 256 + threadIdx.x;
    int s = e & (Ss - 1);
    int j = (e >> 11) & 15;
    int bh = e >> 15;
    int jm = j & (Rr - 1);
    int nidx = (bh * Rr + jm) * Ss + s;
    int sv = snod[nidx];
    if (j == 0 || sv < 0) return;
    int ev = enod[nidx];
    int qn = (j < Rr) ? ev : sv;
    int kn = (j < Rr) ? sv : ev;
    qn &= (Ss - 1); kn &= (Ss - 1);
    int pos = g_off[bh * (Ss + 1) + qn] + atomicAdd(&g_cnt[bh * Ss + qn], 1);
    int idx = bh * (TR * Ss) + pos;
    g_info[idx] = kn | (j << 12);
    g_val[idx] = g_e[e];
}

// ---------------- per-node gather + softmax + weighted sum -------------------
__global__ __launch_bounds__(256) void k_aggr(const float* __restrict__ rv)
{
    int w = (blockIdx.x * 256 + threadIdx.x) >> 5;
    int lane = threadIdx.x & 31;
    int bh = w >> 11;
    int n = w & (Ss - 1);
    int h = bh & (Hh - 1), b = bh >> 3;
    int obase = bh * (Ss + 1) + n;
    int beg = g_off[obase], end = g_off[obase + 1];
    float acc0 = 0.f, acc1 = 0.f, ds = 0.f;
    int cbase = bh * (TR * Ss);
    for (int i = beg; i < end; i++) {
        int info = g_info[cbase + i];
        float evv = g_val[cbase + i];
        int kn = info & 0xFFF;
        int j = info >> 12;
        size_t vb = (size_t)(bh * Ss + kn) * DK;
        int rb = (h * TR + j) * DK;
        acc0 += evv * (g_v[vb + lane] + rv[rb + lane]);
        acc1 += evv * (g_v[vb + 32 + lane] + rv[rb + 32 + lane]);
        ds += evv;
    }
    float inv = ds > 0.f ? 1.f / ds : 0.f;
    size_t ob = (size_t)((b * Ss + n) * Hh + h) * DK;
    g_attn[ob + lane] = acc0 * inv;
    g_attn[ob + 32 + lane] = acc1 * inv;
}

// ---------------- launch --------------------------------------------------
#define GEMM_SMEM (2 * STG_SZ)

extern "C" void kernel_launch(void* const* d_in, const int* in_sizes, int n_in,
                              void* d_out, int out_size)
{
    const float* query = (const float*)d_in[0];
    const float* key   = (const float*)d_in[1];
    const float* value = (const float*)d_in[2];
    const int*   snod  = (const int*)d_in[3];
    const int*   enod  = (const int*)d_in[4];
    const float* rel_q = (const float*)d_in[5];
    const float* rel_k = (const float*)d_in[6];
    const float* rel_v = (const float*)d_in[7];
    const float* Wq = (const float*)d_in[8];
    const float* bq = (const float*)d_in[9];
    const float* Wk = (const float*)d_in[10];
    const float* bk = (const float*)d_in[11];
    const float* Wv = (const float*)d_in[12];
    const float* bv = (const float*)d_in[13];
    const float* Wo = (const float*)d_in[14];
    const float* bo = (const float*)d_in[15];
    float* out = (float*)d_out;

    cudaFuncSetAttribute(gemm_tc, cudaFuncAttributeMaxDynamicSharedMemorySize, GEMM_SMEM);

    dim3 gg(Dd / 128, (Bb * Ss) / 128);   // (4, 64)

    k_zero<<<NNODES / 256, 256>>>();
    gemm_tc<<<gg, 256, GEMM_SMEM>>>(query, Wq, bq, nullptr, 0);
    gemm_tc<<<gg, 256, GEMM_SMEM>>>(key,   Wk, bk, nullptr, 1);
    gemm_tc<<<gg, 256, GEMM_SMEM>>>(value, Wv, bv, nullptr, 2);
    k_edges<<<(size_t)NEDGE * 16 / 256, 256>>>(snod, enod, rel_q, rel_k);
    k_scan<<<NBH, 256>>>();
    k_fill<<<NEDGE / 256, 256>>>(snod, enod);
    k_aggr<<<NNODES * 32 / 256, 256>>>(rel_v);
    gemm_tc<<<gg, 256, GEMM_SMEM>>>(nullptr, Wo, bo, out, 3);
}